// round 14
// baseline (speedup 1.0000x reference)
#include <cuda_runtime.h>
#include <math.h>

#define B_  32
#define S_  50
#define Q_  75
#define T_  128
#define F_  64
#define D_  256
#define KW  5
#define NS  (B_*S_)          // 1600 support samples
#define NQ  (B_*Q_)          // 2400 query samples
#define NTOT (NS+NQ)         // 4000
#define POOLB (NTOT/4)       // 1000 pool blocks (4 samples each, 64 thr/sample)

// Scratch (device globals: allocation-free per harness rules)
__device__ float g_spooled[NS * F_];     // pooled support (400 KB, L2-hot)
__device__ float g_qfeat[NQ * F_];       // pooled queries (600 KB)
__device__ float g_G[F_ * F_];           // Gram G = W W^T (16 KB, L2-resident)
__device__ float g_h[B_ * KW * F_];      // h_k = G p_k
__device__ float g_c[B_ * KW];           // c_k = p_k . h_k

// ---------------------------------------------------------------------------
// K1: pool + gram in ONE launch (unchanged from R13 — measured ~21us @ ~80% of
// the LTS cap for the 131 MB stream).
// ---------------------------------------------------------------------------
__global__ void __launch_bounds__(256) poolgram_kernel(const float* __restrict__ sx,
                                                       const float* __restrict__ qx,
                                                       const float* __restrict__ Wm) {
    int tid = threadIdx.x;

    if (blockIdx.x < POOLB) {
        int lane    = tid & 31;
        int s_local = tid >> 6;          // 0..3
        int wis     = (tid >> 5) & 1;    // warp-in-sample
        int th      = lane >> 4;         // 0..1
        int f4      = lane & 15;         // 0..15

        int sn = blockIdx.x * 4 + s_local;
        const float4* src;
        float4* dstbase;
        if (sn < NS) {
            src     = reinterpret_cast<const float4*>(sx) + (size_t)sn * (T_ * F_ / 4);
            dstbase = reinterpret_cast<float4*>(g_spooled);
        } else {
            src     = reinterpret_cast<const float4*>(qx) + (size_t)(sn - NS) * (T_ * F_ / 4);
            dstbase = reinterpret_cast<float4*>(g_qfeat) - (size_t)NS * 16;
        }

        const float4* p = src + (wis * 64 + th) * 16 + f4;
        float4 a0 = make_float4(0.f,0.f,0.f,0.f);
        float4 a1 = make_float4(0.f,0.f,0.f,0.f);
        float4 a2 = make_float4(0.f,0.f,0.f,0.f);
        float4 a3 = make_float4(0.f,0.f,0.f,0.f);
        #pragma unroll 4
        for (int i = 0; i < 32; i += 4) {
            float4 v0 = p[(2 * i)     * 16];
            float4 v1 = p[(2 * i + 2) * 16];
            float4 v2 = p[(2 * i + 4) * 16];
            float4 v3 = p[(2 * i + 6) * 16];
            a0.x += v0.x; a0.y += v0.y; a0.z += v0.z; a0.w += v0.w;
            a1.x += v1.x; a1.y += v1.y; a1.z += v1.z; a1.w += v1.w;
            a2.x += v2.x; a2.y += v2.y; a2.z += v2.z; a2.w += v2.w;
            a3.x += v3.x; a3.y += v3.y; a3.z += v3.z; a3.w += v3.w;
        }
        float4 a;
        a.x = (a0.x + a1.x) + (a2.x + a3.x);
        a.y = (a0.y + a1.y) + (a2.y + a3.y);
        a.z = (a0.z + a1.z) + (a2.z + a3.z);
        a.w = (a0.w + a1.w) + (a2.w + a3.w);
        a.x += __shfl_xor_sync(0xffffffffu, a.x, 16);
        a.y += __shfl_xor_sync(0xffffffffu, a.y, 16);
        a.z += __shfl_xor_sync(0xffffffffu, a.z, 16);
        a.w += __shfl_xor_sync(0xffffffffu, a.w, 16);

        __shared__ float4 part[4][2][16];
        if (th == 0) part[s_local][wis][f4] = a;
        __syncthreads();

        if (tid < 64) {
            int s = tid >> 4;
            int f = tid & 15;
            float4 u = part[s][0][f];
            float4 v = part[s][1][f];
            const float inv = 1.0f / (float)T_;
            float4 r;
            r.x = (u.x + v.x) * inv;
            r.y = (u.y + v.y) * inv;
            r.z = (u.z + v.z) * inv;
            r.w = (u.w + v.w) * inv;
            dstbase[(blockIdx.x * 4 + s) * 16 + f] = r;
        }
    } else {
        // ---- gram: block computes G row i; warp w owns j = w*8..w*8+7 ----
        int i    = blockIdx.x - POOLB;
        int warp = tid >> 5;
        int lane = tid & 31;

        float wi[8];
        #pragma unroll
        for (int u = 0; u < 8; u++)
            wi[u] = Wm[i * D_ + lane + 32 * u];

        float s[8];
        #pragma unroll
        for (int jj = 0; jj < 8; jj++) s[jj] = 0.f;

        #pragma unroll
        for (int u = 0; u < 8; u++) {
            #pragma unroll
            for (int jj = 0; jj < 8; jj++)
                s[jj] = fmaf(wi[u], Wm[(warp * 8 + jj) * D_ + lane + 32 * u], s[jj]);
        }

        #pragma unroll
        for (int jj = 0; jj < 8; jj++) {
            #pragma unroll
            for (int off = 16; off > 0; off >>= 1)
                s[jj] += __shfl_xor_sync(0xffffffffu, s[jj], off);
        }
        if (lane == 0) {
            #pragma unroll
            for (int jj = 0; jj < 8; jj++)
                g_G[i * F_ + warp * 8 + jj] = s[jj];
        }
    }
}

// ---------------------------------------------------------------------------
// K2: per-episode prototypes + h_k = G p_k + c_k = p_k.h_k.
// One block per episode, 64 threads (thread = feature f). Small + fast.
// ---------------------------------------------------------------------------
__global__ void __launch_bounds__(64) proto_kernel(const int* __restrict__ y) {
    int b = blockIdx.x;
    int f = threadIdx.x;

    __shared__ int   ys[S_];
    __shared__ float psh[KW][F_];
    __shared__ float csh[KW][F_];

    if (f < S_) ys[f] = y[b * S_ + f];
    __syncthreads();

    float a0=0.f,a1=0.f,a2=0.f,a3=0.f,a4=0.f;
    int   c0=0,c1=0,c2=0,c3=0,c4=0;
    #pragma unroll 10
    for (int s = 0; s < S_; s++) {
        float v = g_spooled[(b * S_ + s) * F_ + f];
        int l = ys[s];
        if (l == 0) { a0 += v; c0++; }
        if (l == 1) { a1 += v; c1++; }
        if (l == 2) { a2 += v; c2++; }
        if (l == 3) { a3 += v; c3++; }
        if (l == 4) { a4 += v; c4++; }
    }
    psh[0][f] = c0 ? a0 / (float)c0 : 0.f;
    psh[1][f] = c1 ? a1 / (float)c1 : 0.f;
    psh[2][f] = c2 ? a2 / (float)c2 : 0.f;
    psh[3][f] = c3 ? a3 / (float)c3 : 0.f;
    psh[4][f] = c4 ? a4 / (float)c4 : 0.f;
    __syncthreads();

    float hk[KW];
    #pragma unroll
    for (int k = 0; k < KW; k++) hk[k] = 0.f;
    #pragma unroll 8
    for (int i = 0; i < F_; i++) {
        float gi = g_G[i * F_ + f];   // G symmetric -> coalesced rows
        #pragma unroll
        for (int k = 0; k < KW; k++)
            hk[k] = fmaf(gi, psh[k][i], hk[k]);
    }
    #pragma unroll
    for (int k = 0; k < KW; k++) {
        g_h[(b * KW + k) * F_ + f] = hk[k];
        csh[k][f] = psh[k][f] * hk[k];
    }
    __syncthreads();

    if (f < 32) {
        #pragma unroll
        for (int k = 0; k < KW; k++) {
            float v = csh[k][f] + csh[k][f + 32];
            #pragma unroll
            for (int off = 16; off > 0; off >>= 1)
                v += __shfl_xor_sync(0xffffffffu, v, off);
            if (f == 0) g_c[b * KW + k] = v;
        }
    }
}

// ---------------------------------------------------------------------------
// K3: dist, thread-parallel matvec. 150 blocks x 256 threads, 16 queries/block.
// thread = (q_local = tid>>4, jg = tid&15): computes e_j = (G q)_j for its 4
// j's via 64 pipelined iterations (LDS bcast + LDS.128 + 4 indep FMA — no
// cross-iter dependency), then partial a = sum e_j q_j and partial s_k over
// its 4 f's. ONE 16-lane shfl tree reduces {a, s0..s4}. jg==0 writes 5 logits.
// ---------------------------------------------------------------------------
#define QPB 16
__global__ void __launch_bounds__(256) dist_kernel(float* __restrict__ out) {
    int tid     = threadIdx.x;
    int q_local = tid >> 4;          // 0..15
    int jg      = tid & 15;          // 0..15 -> columns jg*4..jg*4+3
    int qbase   = blockIdx.x * QPB;  // 150*16 = 2400 exactly
    int bq      = qbase + q_local;
    int b0      = qbase / Q_;
    int b1      = (qbase + QPB - 1) / Q_;   // block straddles <= 2 episodes

    __shared__ float Gs[F_ * F_];           // 16 KB (row k, col j)
    __shared__ float Qs[QPB][68];           // padded rows: bank-shift for bcast
    __shared__ float hsh[2][KW][F_];        // 2.5 KB
    __shared__ float csh[2][KW];

    {   // stage G
        const float4* gsrc = reinterpret_cast<const float4*>(g_G);
        float4* gdst = reinterpret_cast<float4*>(Gs);
        #pragma unroll
        for (int u = 0; u < 4; u++) gdst[tid + 256 * u] = gsrc[tid + 256 * u];
        // stage Qf rows (16 float4 per row; consecutive threads -> coalesced)
        int row = tid >> 4, c = tid & 15;
        float4 qv = reinterpret_cast<const float4*>(g_qfeat)[(qbase + row) * 16 + c];
        *reinterpret_cast<float4*>(&Qs[row][c * 4]) = qv;
        // stage h for the (up to) 2 episodes + c
        for (int i = tid; i < 2 * KW * F_; i += 256) {
            int eb = i / (KW * F_);
            int be = eb ? b1 : b0;
            hsh[0][0][i] = g_h[be * KW * F_ + (i - eb * KW * F_)];
        }
        if (tid < 2 * KW) {
            int eb = tid / KW;
            csh[eb][tid % KW] = g_c[(eb ? b1 : b0) * KW + tid % KW];
        }
    }
    __syncthreads();

    // e_j for j = jg*4 .. jg*4+3
    float e0 = 0.f, e1 = 0.f, e2 = 0.f, e3 = 0.f;
    #pragma unroll 16
    for (int k = 0; k < F_; k++) {
        float qk = Qs[q_local][k];
        float4 g = *reinterpret_cast<const float4*>(&Gs[k * F_ + jg * 4]);
        e0 = fmaf(g.x, qk, e0);
        e1 = fmaf(g.y, qk, e1);
        e2 = fmaf(g.z, qk, e2);
        e3 = fmaf(g.w, qk, e3);
    }
    float4 qj = *reinterpret_cast<const float4*>(&Qs[q_local][jg * 4]);
    float a = e0 * qj.x + e1 * qj.y + e2 * qj.z + e3 * qj.w;

    int b  = bq / Q_;
    int eb = b - b0;
    float s[KW];
    #pragma unroll
    for (int k = 0; k < KW; k++) {
        float4 h4 = *reinterpret_cast<const float4*>(&hsh[eb][k][jg * 4]);
        s[k] = qj.x * h4.x + qj.y * h4.y + qj.z * h4.z + qj.w * h4.w;
    }

    // 16-lane tree reduce of {a, s0..s4} (jg groups are 16-lane aligned)
    #pragma unroll
    for (int off = 8; off > 0; off >>= 1) {
        a += __shfl_xor_sync(0xffffffffu, a, off);
        #pragma unroll
        for (int k = 0; k < KW; k++)
            s[k] += __shfl_xor_sync(0xffffffffu, s[k], off);
    }

    if (jg == 0) {
        #pragma unroll
        for (int k = 0; k < KW; k++)
            out[bq * KW + k] = -sqrtf(fmaxf(a - 2.f * s[k] + csh[eb][k], 0.f));
    }
}

// ---------------------------------------------------------------------------
// Inputs (metadata order): support_x f32, support_y i32, query_x f32, W f32, b f32
// Output: f32 [B*Q, KW] = [2400, 5]
// ---------------------------------------------------------------------------
extern "C" void kernel_launch(void* const* d_in, const int* in_sizes, int n_in,
                              void* d_out, int out_size) {
    const float* sx = (const float*)d_in[0];
    const int*   sy = (const int*)  d_in[1];
    const float* qx = (const float*)d_in[2];
    const float* Wm = (const float*)d_in[3];
    float* out = (float*)d_out;

    poolgram_kernel<<<POOLB + F_, 256>>>(sx, qx, Wm);
    proto_kernel   <<<B_,          64>>>(sy);
    dist_kernel    <<<NQ / QPB,   256>>>(out);
}